// round 4
// baseline (speedup 1.0000x reference)
#include <cuda_runtime.h>
#include <math.h>

#define NBAGS 65536
#define EPSF 1e-7f
#define LN2F 0.69314718055994531f

// packed word per bag (positives only):
//   [0:44)  pos sum of log2(1-p+eps), fixed point 2^-22, mod 2^44
//   [44:64) count/borrow headroom (only tested for nonzero)
__device__ unsigned long long g_packed[NBAGS];
__device__ unsigned char      g_neg_present[NBAGS];
// 0: neg_sum_log2, 1: num_neg_bags, 2: num_pos_bags, 3: pos_per_bag_sum
__device__ float        g_accum[4];
__device__ unsigned int g_done;

#define FIX_SCALE 4194304.0f          /* 2^22 */
#define INV_FIX   2.38418579e-7f      /* 2^-22 */
#define MASK44    ((1ULL << 44) - 1)

__global__ void mil_init_kernel() {
    int i = blockIdx.x * blockDim.x + threadIdx.x;
    // zero g_packed as 64K ulonglongs and presence as 16K uint4s
    if (i < NBAGS) g_packed[i] = 0ULL;
    if (i < NBAGS / 4) ((unsigned int*)g_neg_present)[i] = 0u;
    if (i < 4)  g_accum[i] = 0.0f;
    if (i == 4) g_done = 0u;
}

__device__ __forceinline__ void mil_process(float p, int l, int b, float& local2) {
    float t = fmaf(p, -1.0f, 1.0f + EPSF);      // 1 - p + eps (FFMA-imm)
    if (l == 0) {
        local2 += __log2f(t);
        g_neg_present[b] = 1;                    // idempotent scattered byte store
    } else {
        int fx = __float2int_rn(__log2f(t) * FIX_SCALE);   // >= -9.8e7, fits i32
        unsigned long long add = (1ULL << 44) + ((unsigned long long)(long long)fx & MASK44);
        atomicAdd(&g_packed[b], add);            // no return -> RED.64
    }
}

__global__ void __launch_bounds__(256) mil_main_kernel(
        const float4* __restrict__ p4,
        const int4* __restrict__ l4,
        const int4* __restrict__ b4,
        int n4, int n_total,
        const float* __restrict__ p_s,
        const int* __restrict__ l_s,
        const int* __restrict__ b_s) {
    int stride = gridDim.x * blockDim.x;
    float local2 = 0.0f;     // sum of log2(1-p+eps) over negatives

    for (int i = blockIdx.x * blockDim.x + threadIdx.x; i < n4; i += stride) {
        float4 p = p4[i];
        int4   l = l4[i];
        int4   b = b4[i];
        mil_process(p.x, l.x, b.x, local2);
        mil_process(p.y, l.y, b.y, local2);
        mil_process(p.z, l.z, b.z, local2);
        mil_process(p.w, l.w, b.w, local2);
    }
    for (int j = n4 * 4 + blockIdx.x * blockDim.x + threadIdx.x;
         j < n_total; j += stride) {
        mil_process(p_s[j], l_s[j], b_s[j], local2);
    }

    __shared__ float warp_sums[8];
    int lane = threadIdx.x & 31;
    int wid  = threadIdx.x >> 5;
    #pragma unroll
    for (int off = 16; off > 0; off >>= 1)
        local2 += __shfl_down_sync(0xFFFFFFFFu, local2, off);
    if (lane == 0) warp_sums[wid] = local2;
    __syncthreads();
    if (wid == 0) {
        float v = (lane < 8) ? warp_sums[lane] : 0.0f;
        #pragma unroll
        for (int off = 4; off > 0; off >>= 1)
            v += __shfl_down_sync(0xFFFFFFFFu, v, off);
        if (lane == 0) atomicAdd(&g_accum[0], v);
    }
}

// bag decode + partial reduce + (last block) final scalar
__global__ void __launch_bounds__(256) mil_bag_final_kernel(float* out) {
    int i = blockIdx.x * blockDim.x + threadIdx.x;
    float nneg = 0.0f, npos = 0.0f, psum = 0.0f;
    if (i < NBAGS) {
        if (g_neg_present[i]) nneg = 1.0f;
        unsigned long long W = g_packed[i];
        if (W != 0ULL) {
            npos = 1.0f;
            unsigned long long low44 = W & MASK44;
            long long s_fixed = (low44 >= (1ULL << 43))
                ? (long long)low44 - (1LL << 44)
                : (long long)low44;
            float seg = (float)s_fixed * (INV_FIX * LN2F);  // back to natural log
            float v = fminf(expf(seg), 1.0f);
            psum = logf(1.0f - v + EPSF);
        }
    }
    __shared__ float sh[3][8];
    int lane = threadIdx.x & 31;
    int wid  = threadIdx.x >> 5;
    #pragma unroll
    for (int off = 16; off > 0; off >>= 1) {
        nneg += __shfl_down_sync(0xFFFFFFFFu, nneg, off);
        npos += __shfl_down_sync(0xFFFFFFFFu, npos, off);
        psum += __shfl_down_sync(0xFFFFFFFFu, psum, off);
    }
    if (lane == 0) { sh[0][wid] = nneg; sh[1][wid] = npos; sh[2][wid] = psum; }
    __syncthreads();
    bool last = false;
    if (wid == 0) {
        float a = (lane < 8) ? sh[0][lane] : 0.0f;
        float b = (lane < 8) ? sh[1][lane] : 0.0f;
        float c = (lane < 8) ? sh[2][lane] : 0.0f;
        #pragma unroll
        for (int off = 4; off > 0; off >>= 1) {
            a += __shfl_down_sync(0xFFFFFFFFu, a, off);
            b += __shfl_down_sync(0xFFFFFFFFu, b, off);
            c += __shfl_down_sync(0xFFFFFFFFu, c, off);
        }
        if (lane == 0) {
            atomicAdd(&g_accum[1], a);
            atomicAdd(&g_accum[2], b);
            atomicAdd(&g_accum[3], c);
            __threadfence();
            unsigned int t = atomicAdd(&g_done, 1u);
            last = (t == gridDim.x - 1);
        }
    }
    if (last) {
        float neg_sum = g_accum[0] * LN2F;   // log2 -> ln
        float nn      = g_accum[1];
        float np      = g_accum[2];
        float ps      = g_accum[3];
        float neg_loss = (nn > 0.0f) ? (-neg_sum / fmaxf(nn, 1.0f)) : 0.0f;
        float pos_loss = (np > 0.0f) ? (-ps      / fmaxf(np, 1.0f)) : 0.0f;
        out[0] = neg_loss + pos_loss;
    }
}

extern "C" void kernel_launch(void* const* d_in, const int* in_sizes, int n_in,
                              void* d_out, int out_size) {
    const float* probas  = (const float*)d_in[0];
    const int*   labels  = (const int*)d_in[1];
    const int*   bag_ids = (const int*)d_in[2];
    float*       out     = (float*)d_out;
    int n  = in_sizes[0];
    int n4 = n >> 2;

    mil_init_kernel<<<(NBAGS + 255) / 256, 256>>>();

    int blocks = (n4 + 255) / 256;
    const int max_blocks = 148 * 16;
    if (blocks > max_blocks) blocks = max_blocks;
    if (blocks < 1) blocks = 1;
    mil_main_kernel<<<blocks, 256>>>((const float4*)probas, (const int4*)labels,
                                     (const int4*)bag_ids, n4, n,
                                     probas, labels, bag_ids);

    mil_bag_final_kernel<<<NBAGS / 256, 256>>>(out);
}

// round 5
// speedup vs baseline: 1.9567x; 1.9567x over previous
#include <cuda_runtime.h>
#include <math.h>
#include <stdint.h>

#define NBAGS 65536
#define EPSF 1e-7f
#define LN2F 0.69314718055994531f

#define FIX_SCALE 4194304.0f          /* 2^22 */
#define INV_FIX   2.38418579e-7f      /* 2^-22 */
#define MASK44    ((1ULL << 44) - 1)
#define MASK54    ((1ULL << 54) - 1)

#define TILE      2048
#define TILE_B    (TILE * 4)          /* bytes per array per tile: 8192 */
#define NSTAGE    2
/* smem layout: [0:32) 4 mbarriers (full0,empty0,full1,empty1), pad to 64,
   then P[2][TILE] f32, L[2][TILE] i32, B[2][TILE] i32 */
#define OFF_P     64
#define OFF_L     (OFF_P + NSTAGE * TILE_B)
#define OFF_B     (OFF_L + NSTAGE * TILE_B)
#define SMEM_TOT  (OFF_B + NSTAGE * TILE_B)

// packed word per bag: [0:44) pos log2-sum fx22 (mod 2^44), [44:54) pos cnt+borrow, [54:64) neg cnt
__device__ unsigned long long g_packed[NBAGS];
// 0: neg_sum_log2, 1: num_neg_bags, 2: num_pos_bags, 3: pos_per_bag_sum
__device__ float        g_accum[4];
__device__ unsigned int g_done;

__global__ void mil_init_kernel() {
    int i = blockIdx.x * blockDim.x + threadIdx.x;
    if (i < NBAGS) g_packed[i] = 0ULL;
    if (i < 4)     g_accum[i] = 0.0f;
    if (i == 4)    g_done = 0u;
}

__device__ __forceinline__ uint32_t smem_u32(const void* p) {
    uint32_t a;
    asm("{ .reg .u64 t; cvta.to.shared.u64 t, %1; cvt.u32.u64 %0, t; }" : "=r"(a) : "l"(p));
    return a;
}
__device__ __forceinline__ void mbar_init(uint32_t m, uint32_t cnt) {
    asm volatile("mbarrier.init.shared.b64 [%0], %1;" :: "r"(m), "r"(cnt) : "memory");
}
__device__ __forceinline__ void mbar_expect_tx(uint32_t m, uint32_t bytes) {
    asm volatile("mbarrier.arrive.expect_tx.shared.b64 _, [%0], %1;" :: "r"(m), "r"(bytes) : "memory");
}
__device__ __forceinline__ void mbar_arrive(uint32_t m) {
    asm volatile("mbarrier.arrive.shared.b64 _, [%0];" :: "r"(m) : "memory");
}
__device__ __forceinline__ void mbar_wait(uint32_t m, uint32_t parity) {
    uint32_t done;
    asm volatile(
        "{\n\t.reg .pred p;\n\t"
        "mbarrier.try_wait.parity.acquire.cta.shared::cta.b64 p, [%1], %2;\n\t"
        "selp.b32 %0, 1, 0, p;\n\t}"
        : "=r"(done) : "r"(m), "r"(parity) : "memory");
    if (!done) {
        asm volatile(
            "{\n\t.reg .pred P1;\n\t"
            "W_%=:\n\t"
            "mbarrier.try_wait.parity.acquire.cta.shared::cta.b64 P1, [%0], %1, 0x989680;\n\t"
            "@P1 bra.uni D_%=;\n\t"
            "bra.uni W_%=;\n\t"
            "D_%=:\n\t}"
            :: "r"(m), "r"(parity) : "memory");
    }
}
__device__ __forceinline__ void bulk_cp(uint32_t dst, const void* src, uint32_t bytes, uint32_t mbar) {
    asm volatile(
        "cp.async.bulk.shared::cta.global.mbarrier::complete_tx::bytes [%0], [%1], %2, [%3];"
        :: "r"(dst), "l"(src), "r"(bytes), "r"(mbar) : "memory");
}

__device__ __forceinline__ void mil_process(float p, int l, int b, float& local2) {
    float t = fmaf(p, -1.0f, 1.0f + EPSF);            // 1 - p + eps
    float lg = __log2f(t);
    bool is_neg = (l == 0);
    int fx = __float2int_rn(lg * FIX_SCALE);          // fits i32 (>= -9.8e7)
    unsigned long long add = is_neg
        ? (1ULL << 54)
        : ((1ULL << 44) + ((unsigned long long)(long long)fx & MASK44));
    atomicAdd(&g_packed[b], add);                     // no return -> RED.64
    local2 += is_neg ? lg : 0.0f;
}

__global__ void __launch_bounds__(256) mil_main_tma(
        const float* __restrict__ probas,
        const int*   __restrict__ labels,
        const int*   __restrict__ bag_ids,
        int n, int ntiles) {
    extern __shared__ char smem[];
    uint32_t sbase = smem_u32(smem);
    const uint32_t full0  = sbase + 0,  empty0 = sbase + 8;
    const uint32_t full1  = sbase + 16, empty1 = sbase + 24;
    int tid = threadIdx.x;

    if (tid == 0) {
        mbar_init(full0, 1);   mbar_init(empty0, 256);
        mbar_init(full1, 1);   mbar_init(empty1, 256);
        asm volatile("fence.proxy.async.shared::cta;" ::: "memory");
    }
    __syncthreads();

    float local2 = 0.0f;

    // tail (indices beyond full tiles) via plain loads — tiny or empty
    for (int j = ntiles * TILE + blockIdx.x * blockDim.x + tid;
         j < n; j += gridDim.x * blockDim.x) {
        mil_process(probas[j], labels[j], bag_ids[j], local2);
    }

    int t0   = blockIdx.x;
    int step = gridDim.x;
    int T    = (t0 < ntiles) ? ((ntiles - 1 - t0) / step + 1) : 0;

    if (tid == 0) {
        if (T > 0) {
            long long e = (long long)t0 * TILE;
            mbar_expect_tx(full0, 3 * TILE_B);
            bulk_cp(sbase + OFF_P,          probas  + e, TILE_B, full0);
            bulk_cp(sbase + OFF_L,          labels  + e, TILE_B, full0);
            bulk_cp(sbase + OFF_B,          bag_ids + e, TILE_B, full0);
        }
        if (T > 1) {
            long long e = (long long)(t0 + step) * TILE;
            mbar_expect_tx(full1, 3 * TILE_B);
            bulk_cp(sbase + OFF_P + TILE_B, probas  + e, TILE_B, full1);
            bulk_cp(sbase + OFF_L + TILE_B, labels  + e, TILE_B, full1);
            bulk_cp(sbase + OFF_B + TILE_B, bag_ids + e, TILE_B, full1);
        }
    }

    for (int k = 0; k < T; k++) {
        int s  = k & 1;
        uint32_t ph = (k >> 1) & 1;
        uint32_t fullb  = s ? full1  : full0;
        uint32_t emptyb = s ? empty1 : empty0;
        mbar_wait(fullb, ph);

        const float4* P = (const float4*)(smem + OFF_P + s * TILE_B);
        const int4*   L = (const int4*)  (smem + OFF_L + s * TILE_B);
        const int4*   B = (const int4*)  (smem + OFF_B + s * TILE_B);
        int base = tid * 2;                 // 2 float4-groups = 8 elements
        #pragma unroll
        for (int g = 0; g < 2; g++) {
            float4 p = P[base + g];
            int4   l = L[base + g];
            int4   b = B[base + g];
            mil_process(p.x, l.x, b.x, local2);
            mil_process(p.y, l.y, b.y, local2);
            mil_process(p.z, l.z, b.z, local2);
            mil_process(p.w, l.w, b.w, local2);
        }
        mbar_arrive(emptyb);

        if (tid == 0 && k + 2 < T) {
            mbar_wait(emptyb, ph);          // wait for this use's 256 arrivals
            long long e = (long long)(t0 + (long long)(k + 2) * step) * TILE;
            mbar_expect_tx(fullb, 3 * TILE_B);
            bulk_cp(sbase + OFF_P + s * TILE_B, probas  + e, TILE_B, fullb);
            bulk_cp(sbase + OFF_L + s * TILE_B, labels  + e, TILE_B, fullb);
            bulk_cp(sbase + OFF_B + s * TILE_B, bag_ids + e, TILE_B, fullb);
        }
    }

    // block reduction of local neg log2-sum
    __shared__ float warp_sums[8];
    int lane = tid & 31, wid = tid >> 5;
    #pragma unroll
    for (int off = 16; off > 0; off >>= 1)
        local2 += __shfl_down_sync(0xFFFFFFFFu, local2, off);
    if (lane == 0) warp_sums[wid] = local2;
    __syncthreads();
    if (wid == 0) {
        float v = (lane < 8) ? warp_sums[lane] : 0.0f;
        #pragma unroll
        for (int off = 4; off > 0; off >>= 1)
            v += __shfl_down_sync(0xFFFFFFFFu, v, off);
        if (lane == 0) atomicAdd(&g_accum[0], v);
    }
}

__global__ void __launch_bounds__(256) mil_bag_final_kernel(float* out) {
    int i = blockIdx.x * blockDim.x + threadIdx.x;
    float nneg = 0.0f, npos = 0.0f, psum = 0.0f;
    if (i < NBAGS) {
        unsigned long long W = g_packed[i];
        if ((unsigned int)(W >> 54)) nneg = 1.0f;
        unsigned long long pos_part = W & MASK54;
        if (pos_part != 0ULL) {
            npos = 1.0f;
            unsigned long long low44 = pos_part & MASK44;
            long long s_fixed = (low44 >= (1ULL << 43))
                ? (long long)low44 - (1LL << 44)
                : (long long)low44;
            float seg = (float)s_fixed * (INV_FIX * LN2F);   // log2 fx -> natural log
            float v = fminf(expf(seg), 1.0f);
            psum = logf(1.0f - v + EPSF);
        }
    }
    __shared__ float sh[3][8];
    int lane = threadIdx.x & 31, wid = threadIdx.x >> 5;
    #pragma unroll
    for (int off = 16; off > 0; off >>= 1) {
        nneg += __shfl_down_sync(0xFFFFFFFFu, nneg, off);
        npos += __shfl_down_sync(0xFFFFFFFFu, npos, off);
        psum += __shfl_down_sync(0xFFFFFFFFu, psum, off);
    }
    if (lane == 0) { sh[0][wid] = nneg; sh[1][wid] = npos; sh[2][wid] = psum; }
    __syncthreads();
    bool last = false;
    if (wid == 0) {
        float a = (lane < 8) ? sh[0][lane] : 0.0f;
        float b = (lane < 8) ? sh[1][lane] : 0.0f;
        float c = (lane < 8) ? sh[2][lane] : 0.0f;
        #pragma unroll
        for (int off = 4; off > 0; off >>= 1) {
            a += __shfl_down_sync(0xFFFFFFFFu, a, off);
            b += __shfl_down_sync(0xFFFFFFFFu, b, off);
            c += __shfl_down_sync(0xFFFFFFFFu, c, off);
        }
        if (lane == 0) {
            atomicAdd(&g_accum[1], a);
            atomicAdd(&g_accum[2], b);
            atomicAdd(&g_accum[3], c);
            __threadfence();
            unsigned int t = atomicAdd(&g_done, 1u);
            last = (t == gridDim.x - 1);
        }
    }
    if (last) {
        float neg_sum = g_accum[0] * LN2F;   // log2 -> ln
        float nn = g_accum[1], np = g_accum[2], ps = g_accum[3];
        float neg_loss = (nn > 0.0f) ? (-neg_sum / fmaxf(nn, 1.0f)) : 0.0f;
        float pos_loss = (np > 0.0f) ? (-ps      / fmaxf(np, 1.0f)) : 0.0f;
        out[0] = neg_loss + pos_loss;
    }
}

extern "C" void kernel_launch(void* const* d_in, const int* in_sizes, int n_in,
                              void* d_out, int out_size) {
    const float* probas  = (const float*)d_in[0];
    const int*   labels  = (const int*)d_in[1];
    const int*   bag_ids = (const int*)d_in[2];
    float*       out     = (float*)d_out;
    int n      = in_sizes[0];
    int ntiles = n / TILE;

    mil_init_kernel<<<(NBAGS + 255) / 256, 256>>>();

    static int smem_set = 0;
    if (!smem_set) {
        cudaFuncSetAttribute(mil_main_tma,
                             cudaFuncAttributeMaxDynamicSharedMemorySize, SMEM_TOT);
        smem_set = 1;
    }
    int blocks = ntiles < 512 ? (ntiles > 0 ? ntiles : 1) : 512;
    mil_main_tma<<<blocks, 256, SMEM_TOT>>>(probas, labels, bag_ids, n, ntiles);

    mil_bag_final_kernel<<<NBAGS / 256, 256>>>(out);
}

// round 6
// speedup vs baseline: 2.0769x; 1.0614x over previous
#include <cuda_runtime.h>
#include <math.h>

#define NBAGS 65536
#define EPSF 1e-7f
#define LN2F 0.69314718055994531f

#define FIX_SCALE 4194304.0f          /* 2^22 */
#define INV_FIX   2.38418579e-7f      /* 2^-22 */
#define MASK44    ((1ULL << 44) - 1)
#define MASK54    ((1ULL << 54) - 1)

// packed word per bag:
//   [0:44)  pos sum of log2(1-p+eps), fixed point 2^-22, mod 2^44 (two's-comp)
//   [44:54) pos count (+borrow; only tested nonzero together with sum)
//   [54:64) neg count (presence)
__device__ unsigned long long g_packed[NBAGS];
// 0: neg_sum_log2, 1: num_neg_bags, 2: num_pos_bags, 3: pos_per_bag_sum
__device__ float        g_accum[4];
__device__ unsigned int g_done;

__global__ void __launch_bounds__(256) mil_init_kernel() {
    int i = blockIdx.x * blockDim.x + threadIdx.x;
    // 64K ulonglongs = 32K ulonglong2 stores
    if (i < NBAGS / 2) ((ulonglong2*)g_packed)[i] = make_ulonglong2(0ULL, 0ULL);
    if (i < 4)  g_accum[i] = 0.0f;
    if (i == 4) g_done = 0u;
}

__device__ __forceinline__ void mil_process(float p, int l, int b, float& local2) {
    float t = fmaf(p, -1.0f, 1.0f + EPSF);           // 1 - p + eps
    float lg = __log2f(t);
    bool is_neg = (l == 0);
    int fx = __float2int_rn(lg * FIX_SCALE);         // >= -9.8e7, fits i32
    unsigned long long add = is_neg
        ? (1ULL << 54)
        : ((1ULL << 44) + ((unsigned long long)(long long)fx & MASK44));
    atomicAdd(&g_packed[b], add);                    // no return -> RED.64
    local2 += is_neg ? lg : 0.0f;
}

__global__ void __launch_bounds__(256) mil_main_kernel(
        const float4* __restrict__ p4,
        const int4* __restrict__ l4,
        const int4* __restrict__ b4,
        int n4, int n_total,
        const float* __restrict__ p_s,
        const int* __restrict__ l_s,
        const int* __restrict__ b_s) {
    int stride = gridDim.x * blockDim.x;
    float local2 = 0.0f;     // sum of log2(1-p+eps) over negatives

    #pragma unroll 2
    for (int i = blockIdx.x * blockDim.x + threadIdx.x; i < n4; i += stride) {
        float4 p = p4[i];
        int4   l = l4[i];
        int4   b = b4[i];
        mil_process(p.x, l.x, b.x, local2);
        mil_process(p.y, l.y, b.y, local2);
        mil_process(p.z, l.z, b.z, local2);
        mil_process(p.w, l.w, b.w, local2);
    }
    // scalar tail (N % 4 != 0)
    for (int j = n4 * 4 + blockIdx.x * blockDim.x + threadIdx.x;
         j < n_total; j += stride) {
        mil_process(p_s[j], l_s[j], b_s[j], local2);
    }

    // block reduction of local neg log2-sum -> 1 atomic per block
    __shared__ float warp_sums[8];
    int lane = threadIdx.x & 31;
    int wid  = threadIdx.x >> 5;
    #pragma unroll
    for (int off = 16; off > 0; off >>= 1)
        local2 += __shfl_down_sync(0xFFFFFFFFu, local2, off);
    if (lane == 0) warp_sums[wid] = local2;
    __syncthreads();
    if (wid == 0) {
        float v = (lane < 8) ? warp_sums[lane] : 0.0f;
        #pragma unroll
        for (int off = 4; off > 0; off >>= 1)
            v += __shfl_down_sync(0xFFFFFFFFu, v, off);
        if (lane == 0) atomicAdd(&g_accum[0], v);
    }
}

// bag decode + partial reduce + (last block) final scalar
__global__ void __launch_bounds__(256) mil_bag_final_kernel(float* out) {
    int i = blockIdx.x * blockDim.x + threadIdx.x;
    float nneg = 0.0f, npos = 0.0f, psum = 0.0f;
    if (i < NBAGS) {
        unsigned long long W = g_packed[i];
        if ((unsigned int)(W >> 54)) nneg = 1.0f;
        unsigned long long pos_part = W & MASK54;
        if (pos_part != 0ULL) {
            npos = 1.0f;
            unsigned long long low44 = pos_part & MASK44;
            long long s_fixed = (low44 >= (1ULL << 43))
                ? (long long)low44 - (1LL << 44)
                : (long long)low44;
            float seg = (float)s_fixed * (INV_FIX * LN2F);   // log2 fx -> natural log
            float v = fminf(expf(seg), 1.0f);
            psum = logf(1.0f - v + EPSF);
        }
    }
    __shared__ float sh[3][8];
    int lane = threadIdx.x & 31, wid = threadIdx.x >> 5;
    #pragma unroll
    for (int off = 16; off > 0; off >>= 1) {
        nneg += __shfl_down_sync(0xFFFFFFFFu, nneg, off);
        npos += __shfl_down_sync(0xFFFFFFFFu, npos, off);
        psum += __shfl_down_sync(0xFFFFFFFFu, psum, off);
    }
    if (lane == 0) { sh[0][wid] = nneg; sh[1][wid] = npos; sh[2][wid] = psum; }
    __syncthreads();
    bool last = false;
    if (wid == 0) {
        float a = (lane < 8) ? sh[0][lane] : 0.0f;
        float b = (lane < 8) ? sh[1][lane] : 0.0f;
        float c = (lane < 8) ? sh[2][lane] : 0.0f;
        #pragma unroll
        for (int off = 4; off > 0; off >>= 1) {
            a += __shfl_down_sync(0xFFFFFFFFu, a, off);
            b += __shfl_down_sync(0xFFFFFFFFu, b, off);
            c += __shfl_down_sync(0xFFFFFFFFu, c, off);
        }
        if (lane == 0) {
            atomicAdd(&g_accum[1], a);
            atomicAdd(&g_accum[2], b);
            atomicAdd(&g_accum[3], c);
            __threadfence();
            unsigned int t = atomicAdd(&g_done, 1u);
            last = (t == gridDim.x - 1);
        }
    }
    if (last) {
        float neg_sum = g_accum[0] * LN2F;   // log2 -> ln
        float nn = g_accum[1], np = g_accum[2], ps = g_accum[3];
        float neg_loss = (nn > 0.0f) ? (-neg_sum / fmaxf(nn, 1.0f)) : 0.0f;
        float pos_loss = (np > 0.0f) ? (-ps      / fmaxf(np, 1.0f)) : 0.0f;
        out[0] = neg_loss + pos_loss;
    }
}

extern "C" void kernel_launch(void* const* d_in, const int* in_sizes, int n_in,
                              void* d_out, int out_size) {
    const float* probas  = (const float*)d_in[0];
    const int*   labels  = (const int*)d_in[1];
    const int*   bag_ids = (const int*)d_in[2];
    float*       out     = (float*)d_out;
    int n  = in_sizes[0];
    int n4 = n >> 2;

    mil_init_kernel<<<(NBAGS / 2 + 255) / 256, 256>>>();

    // single full wave: 148 SMs x 8 blocks of 256 threads
    int blocks = 148 * 8;
    int needed = (n4 + 255) / 256;
    if (blocks > needed) blocks = needed;
    if (blocks < 1) blocks = 1;
    mil_main_kernel<<<blocks, 256>>>((const float4*)probas, (const int4*)labels,
                                     (const int4*)bag_ids, n4, n,
                                     probas, labels, bag_ids);

    mil_bag_final_kernel<<<NBAGS / 256, 256>>>(out);
}

// round 7
// speedup vs baseline: 2.2359x; 1.0766x over previous
#include <cuda_runtime.h>
#include <math.h>

#define NBAGS 65536
#define EPSF 1e-7f
#define LN2F 0.69314718055994531f

#define FIX_SCALE 4194304.0f          /* 2^22 */
#define INV_FIX   2.38418579e-7f      /* 2^-22 */
#define MASK44    ((1ULL << 44) - 1)
#define MASK54    ((1ULL << 54) - 1)

// packed word per bag:
//   [0:44)  pos sum of log2(1-p+eps), fixed point 2^-22, mod 2^44 (two's-comp)
//   [44:54) pos count (+borrow; tested nonzero together with sum)
//   [54:64) neg count (presence)
// Zero-initialized at module load; mil_bag_final_kernel re-zeroes after each use.
__device__ unsigned long long g_packed[NBAGS];
// 0: neg_sum_log2, 1: num_neg_bags, 2: num_pos_bags, 3: pos_per_bag_sum
__device__ float        g_accum[4];
__device__ unsigned int g_done;

__device__ __forceinline__ void mil_process(float p, int l, int b, float& local2) {
    float t = fmaf(p, -1.0f, 1.0f + EPSF);           // 1 - p + eps
    float lg = __log2f(t);
    bool is_neg = (l == 0);
    int fx = __float2int_rn(lg * FIX_SCALE);         // >= -9.8e7, fits i32
    unsigned long long add = is_neg
        ? (1ULL << 54)
        : ((1ULL << 44) + ((unsigned long long)(long long)fx & MASK44));
    atomicAdd(&g_packed[b], add);                    // no return -> RED.64
    local2 += is_neg ? lg : 0.0f;
}

__global__ void __launch_bounds__(256) mil_main_kernel(
        const float4* __restrict__ p4,
        const int4* __restrict__ l4,
        const int4* __restrict__ b4,
        int n4, int n_total,
        const float* __restrict__ p_s,
        const int* __restrict__ l_s,
        const int* __restrict__ b_s) {
    int stride = gridDim.x * blockDim.x;
    float local2 = 0.0f;     // sum of log2(1-p+eps) over negatives

    for (int i = blockIdx.x * blockDim.x + threadIdx.x; i < n4; i += stride) {
        float4 p = __ldcs(p4 + i);     // streaming: evict-first
        int4   l = __ldcs(l4 + i);
        int4   b = __ldcs(b4 + i);
        mil_process(p.x, l.x, b.x, local2);
        mil_process(p.y, l.y, b.y, local2);
        mil_process(p.z, l.z, b.z, local2);
        mil_process(p.w, l.w, b.w, local2);
    }
    // scalar tail (N % 4 != 0)
    for (int j = n4 * 4 + blockIdx.x * blockDim.x + threadIdx.x;
         j < n_total; j += stride) {
        mil_process(p_s[j], l_s[j], b_s[j], local2);
    }

    // block reduction of local neg log2-sum -> 1 atomic per block
    __shared__ float warp_sums[8];
    int lane = threadIdx.x & 31;
    int wid  = threadIdx.x >> 5;
    #pragma unroll
    for (int off = 16; off > 0; off >>= 1)
        local2 += __shfl_down_sync(0xFFFFFFFFu, local2, off);
    if (lane == 0) warp_sums[wid] = local2;
    __syncthreads();
    if (wid == 0) {
        float v = (lane < 8) ? warp_sums[lane] : 0.0f;
        #pragma unroll
        for (int off = 4; off > 0; off >>= 1)
            v += __shfl_down_sync(0xFFFFFFFFu, v, off);
        if (lane == 0) atomicAdd(&g_accum[0], v);
    }
}

// bag decode + partial reduce + self-clean + (last block) final scalar + state reset
__global__ void __launch_bounds__(256) mil_bag_final_kernel(float* out) {
    int i = blockIdx.x * blockDim.x + threadIdx.x;
    float nneg = 0.0f, npos = 0.0f, psum = 0.0f;
    if (i < NBAGS) {
        unsigned long long W = g_packed[i];
        g_packed[i] = 0ULL;                       // re-zero for next replay (coalesced)
        if ((unsigned int)(W >> 54)) nneg = 1.0f;
        unsigned long long pos_part = W & MASK54;
        if (pos_part != 0ULL) {
            npos = 1.0f;
            unsigned long long low44 = pos_part & MASK44;
            long long s_fixed = (low44 >= (1ULL << 43))
                ? (long long)low44 - (1LL << 44)
                : (long long)low44;
            float seg = (float)s_fixed * (INV_FIX * LN2F);   // log2 fx -> natural log
            float v = fminf(expf(seg), 1.0f);
            psum = logf(1.0f - v + EPSF);
        }
    }
    __shared__ float sh[3][8];
    int lane = threadIdx.x & 31, wid = threadIdx.x >> 5;
    #pragma unroll
    for (int off = 16; off > 0; off >>= 1) {
        nneg += __shfl_down_sync(0xFFFFFFFFu, nneg, off);
        npos += __shfl_down_sync(0xFFFFFFFFu, npos, off);
        psum += __shfl_down_sync(0xFFFFFFFFu, psum, off);
    }
    if (lane == 0) { sh[0][wid] = nneg; sh[1][wid] = npos; sh[2][wid] = psum; }
    __syncthreads();
    bool last = false;
    if (wid == 0) {
        float a = (lane < 8) ? sh[0][lane] : 0.0f;
        float b = (lane < 8) ? sh[1][lane] : 0.0f;
        float c = (lane < 8) ? sh[2][lane] : 0.0f;
        #pragma unroll
        for (int off = 4; off > 0; off >>= 1) {
            a += __shfl_down_sync(0xFFFFFFFFu, a, off);
            b += __shfl_down_sync(0xFFFFFFFFu, b, off);
            c += __shfl_down_sync(0xFFFFFFFFu, c, off);
        }
        if (lane == 0) {
            atomicAdd(&g_accum[1], a);
            atomicAdd(&g_accum[2], b);
            atomicAdd(&g_accum[3], c);
            __threadfence();
            unsigned int t = atomicAdd(&g_done, 1u);
            last = (t == gridDim.x - 1);
        }
    }
    if (last) {
        float neg_sum = g_accum[0] * LN2F;   // log2 -> ln
        float nn = g_accum[1], np = g_accum[2], ps = g_accum[3];
        float neg_loss = (nn > 0.0f) ? (-neg_sum / fmaxf(nn, 1.0f)) : 0.0f;
        float pos_loss = (np > 0.0f) ? (-ps      / fmaxf(np, 1.0f)) : 0.0f;
        out[0] = neg_loss + pos_loss;
        // reset accumulator state for the next graph replay
        g_accum[0] = 0.0f; g_accum[1] = 0.0f;
        g_accum[2] = 0.0f; g_accum[3] = 0.0f;
        g_done = 0u;
    }
}

extern "C" void kernel_launch(void* const* d_in, const int* in_sizes, int n_in,
                              void* d_out, int out_size) {
    const float* probas  = (const float*)d_in[0];
    const int*   labels  = (const int*)d_in[1];
    const int*   bag_ids = (const int*)d_in[2];
    float*       out     = (float*)d_out;
    int n  = in_sizes[0];
    int n4 = n >> 2;

    // R3-style grid: up to 16 blocks/SM worth of blocks (2 waves of residency)
    int blocks = (n4 + 255) / 256;
    const int max_blocks = 148 * 16;
    if (blocks > max_blocks) blocks = max_blocks;
    if (blocks < 1) blocks = 1;
    mil_main_kernel<<<blocks, 256>>>((const float4*)probas, (const int4*)labels,
                                     (const int4*)bag_ids, n4, n,
                                     probas, labels, bag_ids);

    mil_bag_final_kernel<<<NBAGS / 256, 256>>>(out);
}